// round 16
// baseline (speedup 1.0000x reference)
#include <cuda_runtime.h>
#include <cuda_bf16.h>
#include <cuda_fp16.h>
#include <cstdint>

#define BB 4
#define CDIM 128
#define ICD 64
#define NPIX 4096
#define LOG2E 1.4426950408889634f
#define QTA 256                // attn queries per CTA (8 warps x 32 rows)
#define KT 64
#define KSPLIT 2
#define SPAN (NPIX / KSPLIT)   // 2048 keys per split
#define NIT (SPAN / KT)        // 32 iters
#define PAD 72                 // f16 per smem row (144 B)
#define NBUF 4                 // KV pipeline depth

// ---------------- scratch (device globals; allocation-free) ----------------
// theta is PRE-SCALED by LOG2E. Projections stored as f16.
__device__ __half g_thetaH[BB * NPIX * ICD];   // [b][n][i]
__device__ __half g_phiH  [BB * NPIX * ICD];   // [b][n][i]
__device__ __half g_gH    [BB * NPIX * ICD];   // [b][n][i]
__device__ __half g_Oh    [BB * KSPLIT * NPIX * ICD];  // partial O, f16 (scaled 2^-10)
__device__ float  g_l     [BB * KSPLIT * NPIX];        // partial row sums (same scale)

__device__ __forceinline__ uint32_t smem_u32(const void* p) {
    uint32_t a;
    asm("{ .reg .u64 t; cvta.to.shared.u64 t, %1; cvt.u32.u64 %0, t; }" : "=r"(a) : "l"(p));
    return a;
}
__device__ __forceinline__ void cp16(uint32_t dst, const void* src) {
    asm volatile("cp.async.cg.shared.global [%0], [%1], 16;" :: "r"(dst), "l"(src));
}
#define CP_COMMIT() asm volatile("cp.async.commit_group;" ::: "memory")
#define CP_WAIT0()  asm volatile("cp.async.wait_group 0;" ::: "memory")

__device__ __forceinline__ void ldm4(uint32_t* r, uint32_t a) {
    asm volatile("ldmatrix.sync.aligned.m8n8.x4.shared.b16 {%0,%1,%2,%3}, [%4];"
                 : "=r"(r[0]), "=r"(r[1]), "=r"(r[2]), "=r"(r[3]) : "r"(a));
}
__device__ __forceinline__ void ldm4t(uint32_t* r, uint32_t a) {
    asm volatile("ldmatrix.sync.aligned.m8n8.x4.trans.shared.b16 {%0,%1,%2,%3}, [%4];"
                 : "=r"(r[0]), "=r"(r[1]), "=r"(r[2]), "=r"(r[3]) : "r"(a));
}
// bf16 in, f32 accum (proj / out kernels)
__device__ __forceinline__ void mma16816(float* d, const uint32_t* a, const uint32_t* b) {
    asm volatile("mma.sync.aligned.m16n8k16.row.col.f32.bf16.bf16.f32 "
                 "{%0,%1,%2,%3}, {%4,%5,%6,%7}, {%8,%9}, {%0,%1,%2,%3};"
                 : "+f"(d[0]), "+f"(d[1]), "+f"(d[2]), "+f"(d[3])
                 : "r"(a[0]), "r"(a[1]), "r"(a[2]), "r"(a[3]), "r"(b[0]), "r"(b[1]));
}
// f16 in, f16 accum (attn S)
__device__ __forceinline__ void mma16816h16(uint32_t* d, const uint32_t* a, const uint32_t* b) {
    asm volatile("mma.sync.aligned.m16n8k16.row.col.f16.f16.f16.f16 "
                 "{%0,%1}, {%2,%3,%4,%5}, {%6,%7}, {%0,%1};"
                 : "+r"(d[0]), "+r"(d[1])
                 : "r"(a[0]), "r"(a[1]), "r"(a[2]), "r"(a[3]), "r"(b[0]), "r"(b[1]));
}
// f16 in, f32 accum (attn PV)
__device__ __forceinline__ void mma16816hf(float* d, const uint32_t* a, const uint32_t* b) {
    asm volatile("mma.sync.aligned.m16n8k16.row.col.f32.f16.f16.f32 "
                 "{%0,%1,%2,%3}, {%4,%5,%6,%7}, {%8,%9}, {%0,%1,%2,%3};"
                 : "+f"(d[0]), "+f"(d[1]), "+f"(d[2]), "+f"(d[3])
                 : "r"(a[0]), "r"(a[1]), "r"(a[2]), "r"(a[3]), "r"(b[0]), "r"(b[1]));
}
__device__ __forceinline__ uint32_t packbf(float a, float b) {
    __nv_bfloat162 v = __floats2bfloat162_rn(a, b);
    return *reinterpret_cast<uint32_t*>(&v);
}
__device__ __forceinline__ uint32_t packh(float a, float b) {
    __half2 v = __floats2half2_rn(a, b);
    return *reinterpret_cast<uint32_t*>(&v);
}
__device__ __forceinline__ uint32_t hadd2u(uint32_t a, uint32_t b) {
    __half2 r = __hadd2(*reinterpret_cast<__half2*>(&a), *reinterpret_cast<__half2*>(&b));
    return *reinterpret_cast<uint32_t*>(&r);
}
__device__ __forceinline__ uint32_t ex2u(uint32_t a) {
    uint32_t d;
    asm("ex2.approx.f16x2 %0, %1;" : "=r"(d) : "r"(a));
    return d;
}

// ============================================================================
// Kernel A: fused 1x1-conv projections via HMMA.
// NOW: 256 threads, 8 warps = 4 m-tiles x 2 i-halves (96 i-rows each).
// Per-warp MMA chain halved (192 -> 96), 16 warps/SM at 2 CTAs/SM.
// ============================================================================
#define PRJ_XS 0
#define PRJ_WS 18432
#define PRJ_BIAS 70656
#define PRJ_SM 71424
#define PRJROW 272
#define PRJXROW 144

__global__ __launch_bounds__(256, 2) void proj_kernel(const float* __restrict__ x,
                            const float* __restrict__ gw, const float* __restrict__ gb,
                            const float* __restrict__ tw, const float* __restrict__ tb,
                            const float* __restrict__ pw, const float* __restrict__ pb)
{
    extern __shared__ char smc[];
    const uint32_t smb = smem_u32(smc);
    const int tid  = threadIdx.x;
    const int lane = tid & 31;
    const int warp = tid >> 5;          // 0..7
    const int b  = blockIdx.y;
    const int n0 = blockIdx.x * 64;

    const int g  = lane >> 3;
    const int l8 = lane & 7;

    const float* xb = x + (size_t)b * CDIM * NPIX + n0;
    #pragma unroll
    for (int i = tid; i < 128 * 16; i += 256) {
        int c = i >> 4, f = i & 15;
        float4 v = *(const float4*)(xb + (size_t)c * NPIX + f * 4);
        uint2 u;
        u.x = packbf(v.x, v.y);
        u.y = packbf(v.z, v.w);
        *(uint2*)(smc + PRJ_XS + c * PRJXROW + f * 8) = u;
    }
    #pragma unroll
    for (int i = tid; i < 192 * 16; i += 256) {
        int r = i >> 4, u = i & 15;
        const float* src = (r < 64) ? (tw + r * 128)
                         : (r < 128) ? (pw + (r - 64) * 128)
                                     : (gw + (r - 128) * 128);
        float4 f0 = *(const float4*)(src + u * 8);
        float4 f1 = *(const float4*)(src + u * 8 + 4);
        uint4 v;
        v.x = packbf(f0.x, f0.y); v.y = packbf(f0.z, f0.w);
        v.z = packbf(f1.x, f1.y); v.w = packbf(f1.z, f1.w);
        *(uint4*)(smc + PRJ_WS + r * PRJROW + u * 16) = v;
    }
    if (tid < 192) {
        float bv = (tid < 64) ? tb[tid] : (tid < 128) ? pb[tid - 64] : gb[tid - 128];
        ((float*)(smc + PRJ_BIAS))[tid] = bv;
    }
    __syncthreads();

    const int wm = (warp >> 1) * 16;    // m-tile (16 pixels)
    const int ih = warp & 1;            // i-half (96 rows)

    uint32_t Ax[8][4];
    #pragma unroll
    for (int kf = 0; kf < 8; kf++)
        ldm4t(Ax[kf], smb + PRJ_XS
                      + (uint32_t)(kf * 16 + (g >> 1) * 8 + l8) * PRJXROW
                      + (uint32_t)(wm + (g & 1) * 8) * 2);

    float D[12][4];
    #pragma unroll
    for (int i = 0; i < 12; i++)
        #pragma unroll
        for (int j = 0; j < 4; j++) D[i][j] = 0.f;

    #pragma unroll
    for (int ib = 0; ib < 6; ib++) {
        int brow = ih * 96 + ib * 16;
        #pragma unroll
        for (int kf = 0; kf < 8; kf++) {
            uint32_t bf[4];
            ldm4(bf, smb + PRJ_WS
                     + (uint32_t)(brow + (g >> 1) * 8 + l8) * PRJROW
                     + (uint32_t)(kf * 16 + (g & 1) * 8) * 2);
            mma16816(D[2 * ib],     Ax[kf], bf);
            mma16816(D[2 * ib + 1], Ax[kf], bf + 2);
        }
    }

    const float* sbias = (const float*)(smc + PRJ_BIAS);
    const int r  = lane >> 2;
    const int c2 = (lane & 3) * 2;
    const size_t nlo = (size_t)(b * NPIX + n0 + wm + r) * ICD;
    const size_t nhi = nlo + 8 * ICD;
    #pragma unroll
    for (int db = 0; db < 12; db++) {
        int ig = ih * 96 + db * 8 + c2;
        float b0 = sbias[ig], b1 = sbias[ig + 1];
        float v0 = D[db][0] + b0, v1 = D[db][1] + b1;
        float v2 = D[db][2] + b0, v3 = D[db][3] + b1;
        __half* dst;
        if (ig < 64) {
            dst = g_thetaH;
            v0 *= LOG2E; v1 *= LOG2E; v2 *= LOG2E; v3 *= LOG2E;
        } else if (ig < 128) dst = g_phiH;
        else                 dst = g_gH;
        int io = ig & 63;
        *(uint32_t*)&dst[nlo + io] = packh(v0, v1);
        *(uint32_t*)&dst[nhi + io] = packh(v2, v3);
    }
}

// ============================================================================
// Kernel B: split-K flash attention, f16 pipeline (round-15, passing).
// Partial O now stored as PACKED f16x2 (halves scratch traffic).
// grid (16 qtiles, KSPLIT, BB) = 128 CTAs, 256 threads (8 warps x 32q).
// ============================================================================
#define SMQ 0
#define SMKV 36864
#define SM_ATTN (36864 + NBUF * 18432)

__global__ __launch_bounds__(256, 1) void attn_kernel()
{
    extern __shared__ char smc[];
    const uint32_t smb = smem_u32(smc);
    const int tid  = threadIdx.x;
    const int lane = tid & 31;
    const int warp = tid >> 5;          // 0..7
    const int b   = blockIdx.z;
    const int sp  = blockIdx.y;
    const int q0  = blockIdx.x * QTA;
    const int s0  = sp * SPAN;
    const int q0w = warp * 32;

    const int g  = lane >> 3;
    const int l8 = lane & 7;
    const int rowA = (g & 1) * 8 + l8;
    const int colA = (g >> 1) * 8;
    const int rowB = (g >> 1) * 8 + l8;
    const int colB = (g & 1) * 8;
    const int rowV = (g & 1) * 8 + l8;
    const int colV = (g >> 1) * 8;

    {
        const __half* th = g_thetaH + ((size_t)(b * NPIX) + q0) * ICD;
        #pragma unroll
        for (int i = tid; i < 2048; i += 256) {
            int row = i >> 3, u = i & 7;
            *(uint4*)(smc + SMQ + row * 144 + u * 16) = *(const uint4*)(th + row * 64 + u * 8);
        }
    }
    __syncthreads();

    uint32_t Aq[2][4][4];
    #pragma unroll
    for (int s = 0; s < 2; s++)
        #pragma unroll
        for (int kf = 0; kf < 4; kf++)
            ldm4(Aq[s][kf], smb + SMQ
                 + (uint32_t)((q0w + s * 16 + rowA) * PAD + kf * 16 + colA) * 2);

    const __half* phH = g_phiH + (size_t)(b * NPIX) * ICD;
    const __half* gvH = g_gH   + (size_t)(b * NPIX) * ICD;
    auto prefetch = [&](int t) {
        const uint32_t kb = smb + SMKV + (t & (NBUF - 1)) * 18432;
        const uint32_t vb = kb + 9216;
        const int k0 = s0 + t * KT;
        #pragma unroll
        for (int i = tid; i < 512; i += 256) {
            int row = i >> 3, u = i & 7;
            cp16(kb + row * 144 + u * 16, phH + (size_t)(k0 + row) * ICD + u * 8);
            cp16(vb + row * 144 + u * 16, gvH + (size_t)(k0 + row) * ICD + u * 8);
        }
        CP_COMMIT();
    };

    prefetch(0);
    prefetch(1);

    float O[2][8][4];
    #pragma unroll
    for (int s = 0; s < 2; s++)
        #pragma unroll
        for (int i = 0; i < 8; i++)
            #pragma unroll
            for (int j = 0; j < 4; j++) O[s][i][j] = 0.f;
    float lsum[2][2] = {{0.f, 0.f}, {0.f, 0.f}};

    const __half2 m10h = __floats2half2_rn(-10.f, -10.f);
    const uint32_t M10 = *reinterpret_cast<const uint32_t*>(&m10h);

    auto process = [&](int t) {
        const uint32_t kb = smb + SMKV + (t & (NBUF - 1)) * 18432;
        const uint32_t vb = kb + 9216;

        uint32_t S[2][4][4];
        #pragma unroll
        for (int s = 0; s < 2; s++)
            #pragma unroll
            for (int c = 0; c < 4; c++)
                #pragma unroll
                for (int j = 0; j < 4; j++) S[s][c][j] = 0u;

        #pragma unroll
        for (int nbp = 0; nbp < 4; nbp++) {
            #pragma unroll
            for (int kf = 0; kf < 4; kf++) {
                uint32_t bf[4];
                ldm4(bf, kb + (uint32_t)((nbp * 16 + rowB) * PAD + kf * 16 + colB) * 2);
                mma16816h16(&S[0][nbp][0], Aq[0][kf], bf);
                mma16816h16(&S[0][nbp][2], Aq[0][kf], bf + 2);
                mma16816h16(&S[1][nbp][0], Aq[1][kf], bf);
                mma16816h16(&S[1][nbp][2], Aq[1][kf], bf + 2);
            }
        }

        #pragma unroll
        for (int c = 0; c < 4; c++) {
            uint32_t a[2][4];
            #pragma unroll
            for (int s = 0; s < 2; s++) {
                a[s][0] = ex2u(hadd2u(S[s][c][0], M10));
                a[s][1] = ex2u(hadd2u(S[s][c][1], M10));
                a[s][2] = ex2u(hadd2u(S[s][c][2], M10));
                a[s][3] = ex2u(hadd2u(S[s][c][3], M10));
                uint32_t h0 = hadd2u(a[s][0], a[s][2]);
                uint32_t h1 = hadd2u(a[s][1], a[s][3]);
                __half2 h0h = *reinterpret_cast<__half2*>(&h0);
                __half2 h1h = *reinterpret_cast<__half2*>(&h1);
                lsum[s][0] += __low2float(h0h) + __high2float(h0h);
                lsum[s][1] += __low2float(h1h) + __high2float(h1h);
            }
            #pragma unroll
            for (int dbp = 0; dbp < 4; dbp++) {
                uint32_t bf[4];
                ldm4t(bf, vb + (uint32_t)((c * 16 + rowV) * PAD + dbp * 16 + colV) * 2);
                mma16816hf(O[0][2 * dbp],     a[0], bf);
                mma16816hf(O[0][2 * dbp + 1], a[0], bf + 2);
                mma16816hf(O[1][2 * dbp],     a[1], bf);
                mma16816hf(O[1][2 * dbp + 1], a[1], bf + 2);
            }
        }
    };

    #pragma unroll 1
    for (int t = 0; t < NIT; t += 2) {
        CP_WAIT0();
        __syncthreads();
        if (t + 2 < NIT) prefetch(t + 2);
        if (t + 3 < NIT) prefetch(t + 3);
        process(t);
        process(t + 1);
    }

    #pragma unroll
    for (int s = 0; s < 2; s++) {
        lsum[s][0] += __shfl_xor_sync(0xffffffffu, lsum[s][0], 1);
        lsum[s][0] += __shfl_xor_sync(0xffffffffu, lsum[s][0], 2);
        lsum[s][1] += __shfl_xor_sync(0xffffffffu, lsum[s][1], 1);
        lsum[s][1] += __shfl_xor_sync(0xffffffffu, lsum[s][1], 2);
    }

    // ---- store partial O as packed f16x2 + l (fp32) ----
    __half* gO = g_Oh + ((size_t)((b * KSPLIT + sp) * NPIX) + q0) * ICD;
    float* gl = g_l + (size_t)(b * KSPLIT + sp) * NPIX + q0;
    #pragma unroll
    for (int s = 0; s < 2; s++) {
        const int r0 = q0w + s * 16 + (lane >> 2);
        #pragma unroll
        for (int dbp = 0; dbp < 4; dbp++) {
            #pragma unroll
            for (int h = 0; h < 2; h++) {
                int c = dbp * 16 + h * 8 + (lane & 3) * 2;
                int o = 2 * dbp + h;
                *(uint32_t*)&gO[(size_t)r0 * ICD + c]       = packh(O[s][o][0], O[s][o][1]);
                *(uint32_t*)&gO[(size_t)(r0 + 8) * ICD + c] = packh(O[s][o][2], O[s][o][3]);
            }
        }
        if ((lane & 3) == 0) {
            gl[r0]     = lsum[s][0];
            gl[r0 + 8] = lsum[s][1];
        }
    }
}

// ============================================================================
// Kernel C: merge splits (f16 partials) + output GEMM + residual.
// 256 threads, 8 warps = 4 q-subtiles x 2 c-halves.
// ============================================================================
#define EPQT 64
#define EP_YS 0
#define EP_W  9216
#define EP_RI 27648
#define EP_SMT 27904
#define EP_SM 62720

__global__ __launch_bounds__(256, 2) void out_kernel(const float* __restrict__ x,
                                                     const float* __restrict__ Ww,
                                                     const float* __restrict__ Wb,
                                                     float* __restrict__ out)
{
    extern __shared__ char smc[];
    const uint32_t smb = smem_u32(smc);
    const int tid  = threadIdx.x;
    const int lane = tid & 31;
    const int warp = tid >> 5;          // 0..7
    const int qsub = warp >> 1;         // 0..3
    const int chal = warp & 1;          // 0..1
    const int b  = blockIdx.y;
    const int q0 = blockIdx.x * EPQT;
    const int q0w = qsub * 16;

    const int g  = lane >> 3;
    const int l8 = lane & 7;
    const int rowA = (g & 1) * 8 + l8;
    const int colA = (g >> 1) * 8;
    const int rowB = (g >> 1) * 8 + l8;
    const int colB = (g & 1) * 8;

    const float* gl0 = g_l + (size_t)(b * KSPLIT + 0) * NPIX + q0;
    const float* gl1 = g_l + (size_t)(b * KSPLIT + 1) * NPIX + q0;
    if (tid < 64)
        ((float*)(smc + EP_RI))[tid] = 1.f / (gl0[tid] + gl1[tid]);

    #pragma unroll
    for (int i = tid; i < 1024; i += 256) {
        int row = i >> 3, u = i & 7;
        const float* s = Ww + row * 64 + u * 8;
        float4 f0 = *(const float4*)s;
        float4 f1 = *(const float4*)(s + 4);
        uint4 v;
        v.x = packbf(f0.x, f0.y); v.y = packbf(f0.z, f0.w);
        v.z = packbf(f1.x, f1.y); v.w = packbf(f1.z, f1.w);
        *(uint4*)(smc + EP_W + row * 144 + u * 16) = v;
    }
    __syncthreads();

    // ---- y = (O0+O1)*rinv -> bf16 smem ys[64][72]; O partials are f16 ----
    const __half* gO0 = g_Oh + ((size_t)((b * KSPLIT + 0) * NPIX) + q0) * ICD;
    const __half* gO1 = g_Oh + ((size_t)((b * KSPLIT + 1) * NPIX) + q0) * ICD;
    const float* rinv = (const float*)(smc + EP_RI);
    #pragma unroll
    for (int i = tid; i < 64 * 8; i += 256) {
        int row = i >> 3, u = i & 7;
        float rv = rinv[row];
        uint4 a = *(const uint4*)(gO0 + (size_t)row * ICD + u * 8);   // 8 halves
        uint4 c = *(const uint4*)(gO1 + (size_t)row * ICD + u * 8);
        const __half2* pa = reinterpret_cast<const __half2*>(&a);
        const __half2* pc = reinterpret_cast<const __half2*>(&c);
        uint4 v;
        uint32_t* pv = reinterpret_cast<uint32_t*>(&v);
        #pragma unroll
        for (int j = 0; j < 4; j++) {
            float2 fa = __half22float2(pa[j]);
            float2 fc = __half22float2(pc[j]);
            pv[j] = packbf((fa.x + fc.x) * rv, (fa.y + fc.y) * rv);
        }
        *(uint4*)(smc + EP_YS + row * 144 + u * 16) = v;
    }
    __syncthreads();

    uint32_t Ay[4][4];
    #pragma unroll
    for (int kf = 0; kf < 4; kf++)
        ldm4(Ay[kf], smb + EP_YS + (uint32_t)((q0w + rowA) * PAD + kf * 16 + colA) * 2);

    float D[8][4];
    #pragma unroll
    for (int i = 0; i < 8; i++)
        #pragma unroll
        for (int j = 0; j < 4; j++) D[i][j] = 0.f;

    #pragma unroll
    for (int nbp = 0; nbp < 4; nbp++) {
        int crow = (chal * 4 + nbp) * 16;
        #pragma unroll
        for (int kf = 0; kf < 4; kf++) {
            uint32_t bf[4];
            ldm4(bf, smb + EP_W + (uint32_t)((crow + rowB) * PAD + kf * 16 + colB) * 2);
            mma16816(D[2 * nbp],     Ay[kf], bf);
            mma16816(D[2 * nbp + 1], Ay[kf], bf + 2);
        }
    }

    float* smt = (float*)(smc + EP_SMT);
    {
        const int qr = q0w + (lane >> 2);
        const int cb = 2 * (lane & 3);
        #pragma unroll
        for (int nb = 0; nb < 8; nb++) {
            int c = (chal * 4 + (nb >> 1)) * 16 + (nb & 1) * 8 + cb;
            smt[(c    ) * 68 + qr    ] = D[nb][0];
            smt[(c + 1) * 68 + qr    ] = D[nb][1];
            smt[(c    ) * 68 + qr + 8] = D[nb][2];
            smt[(c + 1) * 68 + qr + 8] = D[nb][3];
        }
    }
    __syncthreads();

    #pragma unroll
    for (int idx = tid; idx < CDIM * 16; idx += 256) {
        int c = idx >> 4, qf = idx & 15;
        float4 v = *(const float4*)&smt[c * 68 + qf * 4];
        float bv = Wb[c];
        size_t gi = ((size_t)(b * CDIM + c)) * NPIX + q0 + qf * 4;
        float4 xv = *(const float4*)&x[gi];
        v.x += bv + xv.x; v.y += bv + xv.y; v.z += bv + xv.z; v.w += bv + xv.w;
        *(float4*)&out[gi] = v;
    }
}

// ============================================================================
extern "C" void kernel_launch(void* const* d_in, const int* in_sizes, int n_in,
                              void* d_out, int out_size)
{
    const float* x       = (const float*)d_in[0];
    const float* g_w     = (const float*)d_in[1];
    const float* g_b     = (const float*)d_in[2];
    const float* theta_w = (const float*)d_in[3];
    const float* theta_b = (const float*)d_in[4];
    const float* phi_w   = (const float*)d_in[5];
    const float* phi_b   = (const float*)d_in[6];
    const float* W_w     = (const float*)d_in[7];
    const float* W_b     = (const float*)d_in[8];
    float* out = (float*)d_out;

    cudaFuncSetAttribute(proj_kernel, cudaFuncAttributeMaxDynamicSharedMemorySize, PRJ_SM);
    cudaFuncSetAttribute(attn_kernel, cudaFuncAttributeMaxDynamicSharedMemorySize, SM_ATTN);
    cudaFuncSetAttribute(out_kernel,  cudaFuncAttributeMaxDynamicSharedMemorySize, EP_SM);

    proj_kernel<<<dim3(NPIX / 64, BB), 256, PRJ_SM>>>(x, g_w, g_b, theta_w, theta_b, phi_w, phi_b);
    attn_kernel<<<dim3(NPIX / QTA, KSPLIT, BB), 256, SM_ATTN>>>();
    out_kernel<<<dim3(NPIX / EPQT, BB), 256, EP_SM>>>(x, W_w, W_b, out);
}

// round 17
// speedup vs baseline: 1.0290x; 1.0290x over previous
#include <cuda_runtime.h>
#include <cuda_bf16.h>
#include <cstdint>

#define BB 4
#define CDIM 128
#define ICD 64
#define NPIX 4096
#define LOG2E 1.4426950408889634f
#define QTA 256                // attn queries per CTA (8 warps x 32 rows)
#define KT 64
#define KSPLIT 2
#define SPAN (NPIX / KSPLIT)   // 2048 keys per split
#define NIT (SPAN / KT)        // 32 iters
#define PAD 72                 // bf16 per smem row (144 B)

// ---------------- scratch (device globals; allocation-free) ----------------
// theta is PRE-SCALED by LOG2E (so attn can ex2 the raw MMA output).
__device__ __nv_bfloat16 g_thetaB[BB * NPIX * ICD];       // [b][n][i]
__device__ __nv_bfloat16 g_phiB  [BB * NPIX * ICD];       // [b][n][i]
__device__ __nv_bfloat16 g_gB    [BB * NPIX * ICD];       // [b][n][i]
__device__ float         g_O     [BB * KSPLIT * NPIX * ICD];  // partial O
__device__ float         g_l     [BB * KSPLIT * NPIX];        // partial row sums

__device__ __forceinline__ float ex2f(float x) {
    float y; asm("ex2.approx.ftz.f32 %0, %1;" : "=f"(y) : "f"(x)); return y;
}
__device__ __forceinline__ uint32_t smem_u32(const void* p) {
    uint32_t a;
    asm("{ .reg .u64 t; cvta.to.shared.u64 t, %1; cvt.u32.u64 %0, t; }" : "=r"(a) : "l"(p));
    return a;
}
__device__ __forceinline__ void cp16(uint32_t dst, const void* src) {
    asm volatile("cp.async.cg.shared.global [%0], [%1], 16;" :: "r"(dst), "l"(src));
}
#define CP_COMMIT() asm volatile("cp.async.commit_group;" ::: "memory")
#define CP_WAIT0()  asm volatile("cp.async.wait_group 0;" ::: "memory")

__device__ __forceinline__ void ldm4(uint32_t* r, uint32_t a) {
    asm volatile("ldmatrix.sync.aligned.m8n8.x4.shared.b16 {%0,%1,%2,%3}, [%4];"
                 : "=r"(r[0]), "=r"(r[1]), "=r"(r[2]), "=r"(r[3]) : "r"(a));
}
__device__ __forceinline__ void ldm4t(uint32_t* r, uint32_t a) {
    asm volatile("ldmatrix.sync.aligned.m8n8.x4.trans.shared.b16 {%0,%1,%2,%3}, [%4];"
                 : "=r"(r[0]), "=r"(r[1]), "=r"(r[2]), "=r"(r[3]) : "r"(a));
}
__device__ __forceinline__ void mma16816(float* d, const uint32_t* a, const uint32_t* b) {
    asm volatile("mma.sync.aligned.m16n8k16.row.col.f32.bf16.bf16.f32 "
                 "{%0,%1,%2,%3}, {%4,%5,%6,%7}, {%8,%9}, {%0,%1,%2,%3};"
                 : "+f"(d[0]), "+f"(d[1]), "+f"(d[2]), "+f"(d[3])
                 : "r"(a[0]), "r"(a[1]), "r"(a[2]), "r"(a[3]), "r"(b[0]), "r"(b[1]));
}
__device__ __forceinline__ uint32_t packbf(float a, float b) {
    __nv_bfloat162 v = __floats2bfloat162_rn(a, b);
    return *reinterpret_cast<uint32_t*>(&v);
}

// ============================================================================
// Kernel A: fused 1x1-conv projections via HMMA (ROUND-6 version: measured
// ~9.0us). 128-pixel tiles, 256 threads (8 warps x 16 n-rows), grid (32, BB).
// smem: xs 128c x 272B @0, ws 192 x 272B @34816, bias @87040 -> 87808.
// ============================================================================
#define PRJ_XS 0
#define PRJ_WS 34816
#define PRJ_BIAS 87040
#define PRJ_SM 87808
#define PRJROW 272   // bytes per smem row (136 bf16)

__global__ __launch_bounds__(256, 1) void proj_kernel(const float* __restrict__ x,
                            const float* __restrict__ gw, const float* __restrict__ gb,
                            const float* __restrict__ tw, const float* __restrict__ tb,
                            const float* __restrict__ pw, const float* __restrict__ pb)
{
    extern __shared__ char smc[];
    const uint32_t smb = smem_u32(smc);
    const int tid  = threadIdx.x;
    const int lane = tid & 31;
    const int warp = tid >> 5;
    const int b  = blockIdx.y;
    const int n0 = blockIdx.x * 128;

    const int g  = lane >> 3;
    const int l8 = lane & 7;

    // ---- x tile [c][n0..n0+127] fp32 -> bf16 smem xs[c][136] ----
    const float* xb = x + (size_t)b * CDIM * NPIX + n0;
    #pragma unroll
    for (int i = tid; i < 128 * 32; i += 256) {
        int c = i >> 5, f = i & 31;
        float4 v = *(const float4*)(xb + (size_t)c * NPIX + f * 4);
        uint2 u;
        u.x = packbf(v.x, v.y);
        u.y = packbf(v.z, v.w);
        *(uint2*)(smc + PRJ_XS + c * PRJROW + f * 8) = u;
    }
    // ---- stacked weights [192 i][128 c] fp32 -> bf16 smem ----
    #pragma unroll
    for (int i = tid; i < 192 * 16; i += 256) {
        int r = i >> 4, u = i & 15;
        const float* src = (r < 64) ? (tw + r * 128)
                         : (r < 128) ? (pw + (r - 64) * 128)
                                     : (gw + (r - 128) * 128);
        float4 f0 = *(const float4*)(src + u * 8);
        float4 f1 = *(const float4*)(src + u * 8 + 4);
        uint4 v;
        v.x = packbf(f0.x, f0.y); v.y = packbf(f0.z, f0.w);
        v.z = packbf(f1.x, f1.y); v.w = packbf(f1.z, f1.w);
        *(uint4*)(smc + PRJ_WS + r * PRJROW + u * 16) = v;
    }
    if (tid < 192) {
        float bv = (tid < 64) ? tb[tid] : (tid < 128) ? pb[tid - 64] : gb[tid - 128];
        ((float*)(smc + PRJ_BIAS))[tid] = bv;
    }
    __syncthreads();

    const int wm = warp * 16;

    uint32_t Ax[8][4];
    #pragma unroll
    for (int kf = 0; kf < 8; kf++)
        ldm4t(Ax[kf], smb + PRJ_XS
                      + (uint32_t)(kf * 16 + (g >> 1) * 8 + l8) * PRJROW
                      + (uint32_t)(wm + (g & 1) * 8) * 2);

    float D[24][4];
    #pragma unroll
    for (int i = 0; i < 24; i++)
        #pragma unroll
        for (int j = 0; j < 4; j++) D[i][j] = 0.f;

    #pragma unroll
    for (int ib = 0; ib < 12; ib++) {
        #pragma unroll
        for (int kf = 0; kf < 8; kf++) {
            uint32_t bf[4];
            ldm4(bf, smb + PRJ_WS
                     + (uint32_t)(ib * 16 + (g >> 1) * 8 + l8) * PRJROW
                     + (uint32_t)(kf * 16 + (g & 1) * 8) * 2);
            mma16816(D[2 * ib],     Ax[kf], bf);
            mma16816(D[2 * ib + 1], Ax[kf], bf + 2);
        }
    }

    const float* sbias = (const float*)(smc + PRJ_BIAS);
    const int r  = lane >> 2;
    const int c2 = (lane & 3) * 2;
    const size_t nlo = (size_t)(b * NPIX + n0 + wm + r) * ICD;
    const size_t nhi = nlo + 8 * ICD;
    #pragma unroll
    for (int db = 0; db < 24; db++) {
        int ig = db * 8 + c2;
        float b0 = sbias[ig], b1 = sbias[ig + 1];
        float v0 = D[db][0] + b0, v1 = D[db][1] + b1;
        float v2 = D[db][2] + b0, v3 = D[db][3] + b1;
        __nv_bfloat16* dst;
        if (ig < 64) {
            dst = g_thetaB;
            v0 *= LOG2E; v1 *= LOG2E; v2 *= LOG2E; v3 *= LOG2E;
        } else if (ig < 128) dst = g_phiB;
        else                 dst = g_gB;
        int io = ig & 63;
        *(uint32_t*)&dst[nlo + io] = packbf(v0, v1);
        *(uint32_t*)&dst[nhi + io] = packbf(v2, v3);
    }
}

// ============================================================================
// Kernel B: split-K HMMA flash attention (ROUND-9 version: measured 47.6us).
// grid (16 qtiles, KSPLIT, BB) = 128 CTAs, 256 threads (8 warps x 32q).
// smem: Q 256x144 @0 (36864), KV 4 bufs 64x144 @36864 -> total 73728.
// ============================================================================
#define SMQ 0
#define SMKV 36864
#define SM_ATTN 73728

__global__ __launch_bounds__(256, 1) void attn_kernel()
{
    extern __shared__ char smc[];
    const uint32_t smb = smem_u32(smc);
    const int tid  = threadIdx.x;
    const int lane = tid & 31;
    const int warp = tid >> 5;          // 0..7
    const int b   = blockIdx.z;
    const int sp  = blockIdx.y;
    const int q0  = blockIdx.x * QTA;
    const int s0  = sp * SPAN;
    const int q0w = warp * 32;

    const int g  = lane >> 3;
    const int l8 = lane & 7;
    const int rowA = (g & 1) * 8 + l8;
    const int colA = (g >> 1) * 8;
    const int rowB = (g >> 1) * 8 + l8;
    const int colB = (g & 1) * 8;
    const int rowV = (g & 1) * 8 + l8;
    const int colV = (g >> 1) * 8;

    {
        const __nv_bfloat16* th = g_thetaB + ((size_t)(b * NPIX) + q0) * ICD;
        #pragma unroll
        for (int i = tid; i < 2048; i += 256) {
            int row = i >> 3, u = i & 7;
            *(uint4*)(smc + SMQ + row * 144 + u * 16) = *(const uint4*)(th + row * 64 + u * 8);
        }
    }
    __syncthreads();

    uint32_t Aq[2][4][4];
    #pragma unroll
    for (int s = 0; s < 2; s++)
        #pragma unroll
        for (int kf = 0; kf < 4; kf++)
            ldm4(Aq[s][kf], smb + SMQ
                 + (uint32_t)((q0w + s * 16 + rowA) * PAD + kf * 16 + colA) * 2);

    const __nv_bfloat16* phB = g_phiB + (size_t)(b * NPIX) * ICD;
    const __nv_bfloat16* gvB = g_gB   + (size_t)(b * NPIX) * ICD;
    auto prefetch = [&](int t) {
        const uint32_t kb = smb + SMKV + (t & 1) * 18432;
        const uint32_t vb = kb + 9216;
        const int k0 = s0 + t * KT;
        #pragma unroll
        for (int i = tid; i < 512; i += 256) {
            int row = i >> 3, u = i & 7;
            cp16(kb + row * 144 + u * 16, phB + (size_t)(k0 + row) * ICD + u * 8);
            cp16(vb + row * 144 + u * 16, gvB + (size_t)(k0 + row) * ICD + u * 8);
        }
        CP_COMMIT();
    };

    prefetch(0);

    float O[2][8][4];
    #pragma unroll
    for (int s = 0; s < 2; s++)
        #pragma unroll
        for (int i = 0; i < 8; i++)
            #pragma unroll
            for (int j = 0; j < 4; j++) O[s][i][j] = 0.f;
    float lsum[2][2] = {{0.f, 0.f}, {0.f, 0.f}};

    #pragma unroll 1
    for (int t = 0; t < NIT; t++) {
        CP_WAIT0();
        __syncthreads();
        if (t + 1 < NIT) prefetch(t + 1);

        const uint32_t kb = smb + SMKV + (t & 1) * 18432;
        const uint32_t vb = kb + 9216;

        float S[2][8][4];
        #pragma unroll
        for (int s = 0; s < 2; s++)
            #pragma unroll
            for (int i = 0; i < 8; i++)
                #pragma unroll
                for (int j = 0; j < 4; j++) S[s][i][j] = 0.f;

        #pragma unroll
        for (int nbp = 0; nbp < 4; nbp++) {
            #pragma unroll
            for (int kf = 0; kf < 4; kf++) {
                uint32_t bf[4];
                ldm4(bf, kb + (uint32_t)((nbp * 16 + rowB) * PAD + kf * 16 + colB) * 2);
                mma16816(S[0][2 * nbp],     Aq[0][kf], bf);
                mma16816(S[0][2 * nbp + 1], Aq[0][kf], bf + 2);
                mma16816(S[1][2 * nbp],     Aq[1][kf], bf);
                mma16816(S[1][2 * nbp + 1], Aq[1][kf], bf + 2);
            }
        }

        #pragma unroll
        for (int kf2 = 0; kf2 < 4; kf2++) {
            uint32_t a[2][4];
            #pragma unroll
            for (int s = 0; s < 2; s++) {
                float e0 = ex2f(S[s][2 * kf2][0]);
                float e1 = ex2f(S[s][2 * kf2][1]);
                float e2 = ex2f(S[s][2 * kf2][2]);
                float e3 = ex2f(S[s][2 * kf2][3]);
                float e4 = ex2f(S[s][2 * kf2 + 1][0]);
                float e5 = ex2f(S[s][2 * kf2 + 1][1]);
                float e6 = ex2f(S[s][2 * kf2 + 1][2]);
                float e7 = ex2f(S[s][2 * kf2 + 1][3]);
                lsum[s][0] += (e0 + e1) + (e4 + e5);
                lsum[s][1] += (e2 + e3) + (e6 + e7);
                a[s][0] = packbf(e0, e1);
                a[s][1] = packbf(e2, e3);
                a[s][2] = packbf(e4, e5);
                a[s][3] = packbf(e6, e7);
            }
            #pragma unroll
            for (int dbp = 0; dbp < 4; dbp++) {
                uint32_t bf[4];
                ldm4t(bf, vb + (uint32_t)((kf2 * 16 + rowV) * PAD + dbp * 16 + colV) * 2);
                mma16816(O[0][2 * dbp],     a[0], bf);
                mma16816(O[0][2 * dbp + 1], a[0], bf + 2);
                mma16816(O[1][2 * dbp],     a[1], bf);
                mma16816(O[1][2 * dbp + 1], a[1], bf + 2);
            }
        }
    }

    #pragma unroll
    for (int s = 0; s < 2; s++) {
        lsum[s][0] += __shfl_xor_sync(0xffffffffu, lsum[s][0], 1);
        lsum[s][0] += __shfl_xor_sync(0xffffffffu, lsum[s][0], 2);
        lsum[s][1] += __shfl_xor_sync(0xffffffffu, lsum[s][1], 1);
        lsum[s][1] += __shfl_xor_sync(0xffffffffu, lsum[s][1], 2);
    }

    float* gO = g_O + ((size_t)((b * KSPLIT + sp) * NPIX) + q0) * ICD;
    float* gl = g_l + (size_t)(b * KSPLIT + sp) * NPIX + q0;
    #pragma unroll
    for (int s = 0; s < 2; s++) {
        const int r0 = q0w + s * 16 + (lane >> 2);
        #pragma unroll
        for (int dbp = 0; dbp < 4; dbp++) {
            #pragma unroll
            for (int h = 0; h < 2; h++) {
                int c = dbp * 16 + h * 8 + (lane & 3) * 2;
                int o = 2 * dbp + h;
                *(float2*)&gO[(size_t)r0 * ICD + c]       = make_float2(O[s][o][0], O[s][o][1]);
                *(float2*)&gO[(size_t)(r0 + 8) * ICD + c] = make_float2(O[s][o][2], O[s][o][3]);
            }
        }
        if ((lane & 3) == 0) {
            gl[r0]     = lsum[s][0];
            gl[r0 + 8] = lsum[s][1];
        }
    }
}

// ============================================================================
// Kernel C: merge splits + output GEMM + residual (ROUND-11 version: 9.4us).
// 256 threads, 8 warps = 4 q-subtiles x 2 c-halves.
// ============================================================================
#define EPQT 64
#define EP_YS 0
#define EP_W  9216
#define EP_RI 27648
#define EP_SMT 27904
#define EP_SM 62720

__global__ __launch_bounds__(256, 2) void out_kernel(const float* __restrict__ x,
                                                     const float* __restrict__ Ww,
                                                     const float* __restrict__ Wb,
                                                     float* __restrict__ out)
{
    extern __shared__ char smc[];
    const uint32_t smb = smem_u32(smc);
    const int tid  = threadIdx.x;
    const int lane = tid & 31;
    const int warp = tid >> 5;          // 0..7
    const int qsub = warp >> 1;         // 0..3
    const int chal = warp & 1;          // 0..1
    const int b  = blockIdx.y;
    const int q0 = blockIdx.x * EPQT;
    const int q0w = qsub * 16;

    const int g  = lane >> 3;
    const int l8 = lane & 7;
    const int rowA = (g & 1) * 8 + l8;
    const int colA = (g >> 1) * 8;
    const int rowB = (g >> 1) * 8 + l8;
    const int colB = (g & 1) * 8;

    const float* gl0 = g_l + (size_t)(b * KSPLIT + 0) * NPIX + q0;
    const float* gl1 = g_l + (size_t)(b * KSPLIT + 1) * NPIX + q0;
    if (tid < 64)
        ((float*)(smc + EP_RI))[tid] = 1.f / (gl0[tid] + gl1[tid]);

    #pragma unroll
    for (int i = tid; i < 1024; i += 256) {
        int row = i >> 3, u = i & 7;
        const float* s = Ww + row * 64 + u * 8;
        float4 f0 = *(const float4*)s;
        float4 f1 = *(const float4*)(s + 4);
        uint4 v;
        v.x = packbf(f0.x, f0.y); v.y = packbf(f0.z, f0.w);
        v.z = packbf(f1.x, f1.y); v.w = packbf(f1.z, f1.w);
        *(uint4*)(smc + EP_W + row * 144 + u * 16) = v;
    }
    __syncthreads();

    const float* gO0 = g_O + ((size_t)((b * KSPLIT + 0) * NPIX) + q0) * ICD;
    const float* gO1 = g_O + ((size_t)((b * KSPLIT + 1) * NPIX) + q0) * ICD;
    const float* rinv = (const float*)(smc + EP_RI);
    #pragma unroll
    for (int i = tid; i < 64 * 8; i += 256) {
        int row = i >> 3, u = i & 7;
        float rv = rinv[row];
        float4 a0 = *(const float4*)(gO0 + (size_t)row * ICD + u * 8);
        float4 a1 = *(const float4*)(gO0 + (size_t)row * ICD + u * 8 + 4);
        float4 b0 = *(const float4*)(gO1 + (size_t)row * ICD + u * 8);
        float4 b1 = *(const float4*)(gO1 + (size_t)row * ICD + u * 8 + 4);
        uint4 v;
        v.x = packbf((a0.x + b0.x) * rv, (a0.y + b0.y) * rv);
        v.y = packbf((a0.z + b0.z) * rv, (a0.w + b0.w) * rv);
        v.z = packbf((a1.x + b1.x) * rv, (a1.y + b1.y) * rv);
        v.w = packbf((a1.z + b1.z) * rv, (a1.w + b1.w) * rv);
        *(uint4*)(smc + EP_YS + row * 144 + u * 16) = v;
    }
    __syncthreads();

    uint32_t Ay[4][4];
    #pragma unroll
    for (int kf = 0; kf < 4; kf++)
        ldm4(Ay[kf], smb + EP_YS + (uint32_t)((q0w + rowA) * PAD + kf * 16 + colA) * 2);

    float D[8][4];
    #pragma unroll
    for (int i = 0; i < 8; i++)
        #pragma unroll
        for (int j = 0; j < 4; j++) D[i][j] = 0.f;

    #pragma unroll
    for (int nbp = 0; nbp < 4; nbp++) {
        int crow = (chal * 4 + nbp) * 16;
        #pragma unroll
        for (int kf = 0; kf < 4; kf++) {
            uint32_t bf[4];
            ldm4(bf, smb + EP_W + (uint32_t)((crow + rowB) * PAD + kf * 16 + colB) * 2);
            mma16816(D[2 * nbp],     Ay[kf], bf);
            mma16816(D[2 * nbp + 1], Ay[kf], bf + 2);
        }
    }

    float* smt = (float*)(smc + EP_SMT);
    {
        const int qr = q0w + (lane >> 2);
        const int cb = 2 * (lane & 3);
        #pragma unroll
        for (int nb = 0; nb < 8; nb++) {
            int c = (chal * 4 + (nb >> 1)) * 16 + (nb & 1) * 8 + cb;
            smt[(c    ) * 68 + qr    ] = D[nb][0];
            smt[(c + 1) * 68 + qr    ] = D[nb][1];
            smt[(c    ) * 68 + qr + 8] = D[nb][2];
            smt[(c + 1) * 68 + qr + 8] = D[nb][3];
        }
    }
    __syncthreads();

    #pragma unroll
    for (int idx = tid; idx < CDIM * 16; idx += 256) {
        int c = idx >> 4, qf = idx & 15;
        float4 v = *(const float4*)&smt[c * 68 + qf * 4];
        float bv = Wb[c];
        size_t gi = ((size_t)(b * CDIM + c)) * NPIX + q0 + qf * 4;
        float4 xv = *(const float4*)&x[gi];
        v.x += bv + xv.x; v.y += bv + xv.y; v.z += bv + xv.z; v.w += bv + xv.w;
        *(float4*)&out[gi] = v;
    }
}

// ============================================================================
extern "C" void kernel_launch(void* const* d_in, const int* in_sizes, int n_in,
                              void* d_out, int out_size)
{
    const float* x       = (const float*)d_in[0];
    const float* g_w     = (const float*)d_in[1];
    const float* g_b     = (const float*)d_in[2];
    const float* theta_w = (const float*)d_in[3];
    const float* theta_b = (const float*)d_in[4];
    const float* phi_w   = (const float*)d_in[5];
    const float* phi_b   = (const float*)d_in[6];
    const float* W_w     = (const float*)d_in[7];
    const float* W_b     = (const float*)d_in[8];
    float* out = (float*)d_out;

    cudaFuncSetAttribute(proj_kernel, cudaFuncAttributeMaxDynamicSharedMemorySize, PRJ_SM);
    cudaFuncSetAttribute(attn_kernel, cudaFuncAttributeMaxDynamicSharedMemorySize, SM_ATTN);
    cudaFuncSetAttribute(out_kernel,  cudaFuncAttributeMaxDynamicSharedMemorySize, EP_SM);

    proj_kernel<<<dim3(NPIX / 128, BB), 256, PRJ_SM>>>(x, g_w, g_b, theta_w, theta_b, phi_w, phi_b);
    attn_kernel<<<dim3(NPIX / QTA, KSPLIT, BB), 256, SM_ATTN>>>();
    out_kernel<<<dim3(NPIX / EPQT, BB), 256, EP_SM>>>(x, W_w, W_b, out);
}